// round 5
// baseline (speedup 1.0000x reference)
#include <cuda_runtime.h>

#define THREADS 128
#define EPSF 1e-12f

typedef unsigned long long ull;

// ---- f32x2 packed helpers (sm_103a) ----
__device__ __forceinline__ ull pack2(float lo, float hi) {
    ull r; asm("mov.b64 %0, {%1, %2};" : "=l"(r) : "f"(lo), "f"(hi)); return r;
}
__device__ __forceinline__ void unpack2(ull p, float& lo, float& hi) {
    asm("mov.b64 {%0, %1}, %2;" : "=f"(lo), "=f"(hi) : "l"(p));
}
__device__ __forceinline__ ull fma2(ull a, ull b, ull c) {
    ull d; asm("fma.rn.f32x2 %0, %1, %2, %3;" : "=l"(d) : "l"(a), "l"(b), "l"(c)); return d;
}
__device__ __forceinline__ ull add2(ull a, ull b) {
    ull d; asm("add.rn.f32x2 %0, %1, %2;" : "=l"(d) : "l"(a), "l"(b)); return d;
}
__device__ __forceinline__ ull mul2(ull a, ull b) {
    ull d; asm("mul.rn.f32x2 %0, %1, %2;" : "=l"(d) : "l"(a), "l"(b)); return d;
}
__device__ __forceinline__ float frcp(float x) {
    float y; asm("rcp.approx.f32 %0, %1;" : "=f"(y) : "f"(x)); return y;
}

// ---- packed-over-two-rows head math + Sinkhorn + store ----
__device__ __forceinline__ void head2(
    const float* __restrict__ xA, const float* __restrict__ xB,
    const float* __restrict__ pA, const float* __restrict__ pB,
    float* __restrict__ out_mus, float* __restrict__ out_V,
    int rowA, int rowB)
{
    ull A00 = pack2(__expf(pA[0]), __expf(pB[0]));
    ull A01 = pack2(__expf(pA[1]), __expf(pB[1]));
    ull A10 = pack2(__expf(pA[2]), __expf(pB[2]));
    ull A11 = pack2(__expf(pA[3]), __expf(pB[3]));
    const ull ONE = pack2(1.0f, 1.0f);
    ull A02 = ONE, A12 = ONE, A20 = ONE, A21 = ONE, A22 = ONE;

    float shm0A = 0.02f + 0.96f * frcp(1.0f + __expf(-pA[4]));
    float shm1A = 0.02f + 0.96f * frcp(1.0f + __expf(-pA[5]));
    float shf0A = 0.02f + 0.96f * frcp(1.0f + __expf(-pA[6]));
    float shf1A = 0.02f + 0.96f * frcp(1.0f + __expf(-pA[7]));
    float shm0B = 0.02f + 0.96f * frcp(1.0f + __expf(-pB[4]));
    float shm1B = 0.02f + 0.96f * frcp(1.0f + __expf(-pB[5]));
    float shf0B = 0.02f + 0.96f * frcp(1.0f + __expf(-pB[6]));
    float shf1B = 0.02f + 0.96f * frcp(1.0f + __expf(-pB[7]));
    float VA = __expf(pA[8]), VB = __expf(pB[8]);

    ull M0 = pack2(xA[0], xB[0]), M1 = pack2(xA[1], xB[1]), M2 = pack2(xA[2], xB[2]);
    ull F0 = pack2(xA[3], xB[3]), F1 = pack2(xA[4], xB[4]), F2 = pack2(xA[5], xB[5]);
    ull r0 = mul2(M0, pack2(shm0A, shm0B));
    ull r1 = mul2(M1, pack2(shm1A, shm1B));
    ull r2 = M2;
    ull c0 = mul2(F0, pack2(shf0A, shf0B));
    ull c1 = mul2(F1, pack2(shf1A, shf1B));
    ull c2 = F2;

    float um0A = xA[0] * (1.0f - shm0A), um1A = xA[1] * (1.0f - shm1A);
    float uf0A = xA[3] * (1.0f - shf0A), uf1A = xA[4] * (1.0f - shf1A);
    float um0B = xB[0] * (1.0f - shm0B), um1B = xB[1] * (1.0f - shm1B);
    float uf0B = xB[3] * (1.0f - shf0B), uf1B = xB[4] * (1.0f - shf1B);

    const ull EPS2 = pack2(EPSF, EPSF);

    #pragma unroll
    for (int it = 0; it < 10; it++) {
        ull s0 = add2(add2(A00, A01), add2(A02, EPS2));
        ull s1 = add2(add2(A10, A11), add2(A12, EPS2));
        ull s2 = add2(add2(A20, A21), add2(A22, EPS2));
        float l, h;
        unpack2(s0, l, h); ull i0 = pack2(frcp(l), frcp(h));
        unpack2(s1, l, h); ull i1 = pack2(frcp(l), frcp(h));
        unpack2(s2, l, h); ull i2 = pack2(frcp(l), frcp(h));
        ull f0 = mul2(r0, i0), f1 = mul2(r1, i1), f2 = mul2(r2, i2);
        A00 = mul2(A00, f0); A01 = mul2(A01, f0); A02 = mul2(A02, f0);
        A10 = mul2(A10, f1); A11 = mul2(A11, f1); A12 = mul2(A12, f1);
        A20 = mul2(A20, f2); A21 = mul2(A21, f2); A22 = mul2(A22, f2);
        ull t0 = add2(add2(A00, A10), add2(A20, EPS2));
        ull t1 = add2(add2(A01, A11), add2(A21, EPS2));
        ull t2 = add2(add2(A02, A12), add2(A22, EPS2));
        unpack2(t0, l, h); ull j0 = pack2(frcp(l), frcp(h));
        unpack2(t1, l, h); ull j1 = pack2(frcp(l), frcp(h));
        unpack2(t2, l, h); ull j2 = pack2(frcp(l), frcp(h));
        ull g0 = mul2(c0, j0), g1 = mul2(c1, j1), g2 = mul2(c2, j2);
        A00 = mul2(A00, g0); A10 = mul2(A10, g0); A20 = mul2(A20, g0);
        A01 = mul2(A01, g1); A11 = mul2(A11, g1); A21 = mul2(A21, g1);
        A02 = mul2(A02, g2); A12 = mul2(A12, g2); A22 = mul2(A22, g2);
    }

    float a00, a01, a02, a10, a11, a12, a20, a21, a22;
    float b00, b01, b02, b10, b11, b12, b20, b21, b22;
    unpack2(A00, a00, b00); unpack2(A01, a01, b01); unpack2(A02, a02, b02);
    unpack2(A10, a10, b10); unpack2(A11, a11, b11); unpack2(A12, a12, b12);
    unpack2(A20, a20, b20); unpack2(A21, a21, b21); unpack2(A22, a22, b22);

    float4* oA = reinterpret_cast<float4*>(out_mus + (size_t)rowA * 16);
    oA[0] = make_float4(a00, a01, a02, um0A);
    oA[1] = make_float4(a10, a11, a12, um1A);
    oA[2] = make_float4(a20, a21, a22, 0.0f);
    oA[3] = make_float4(uf0A, uf1A, 0.0f, 0.0f);
    out_V[rowA] = VA;

    float4* oB = reinterpret_cast<float4*>(out_mus + (size_t)rowB * 16);
    oB[0] = make_float4(b00, b01, b02, um0B);
    oB[1] = make_float4(b10, b11, b12, um1B);
    oB[2] = make_float4(b20, b21, b22, 0.0f);
    oB[3] = make_float4(uf0B, uf1B, 0.0f, 0.0f);
    out_V[rowB] = VB;
}

__global__ __launch_bounds__(THREADS, 2)
void sinkhorn_unmatched_kernel(
    const float* __restrict__ margins,
    const float* __restrict__ W1, const float* __restrict__ b1,
    const float* __restrict__ W2, const float* __restrict__ b2,
    const float* __restrict__ W3, const float* __restrict__ b3,
    const float* __restrict__ W4, const float* __restrict__ b4,
    float* __restrict__ out_mus, float* __restrict__ out_V, int B)
{
    // shared weights: W1 transposed + (w,w)-duplicated pairs; others raw
    __shared__ ulonglong2 sW1d[64 * 3];
    __shared__ ull        sb1d[64];
    __shared__ float sW2[64 * 32];
    __shared__ float sb2[32];
    __shared__ float sW3[32 * 16];
    __shared__ float sb3[16];
    __shared__ float sW4[16 * 12];
    __shared__ float sb4[12];

    const int tid = threadIdx.x;
    for (int i = tid; i < 64 * 3; i += THREADS) {
        int j = i / 3, p = i % 3;
        float wa = W1[(2 * p + 0) * 64 + j];
        float wb = W1[(2 * p + 1) * 64 + j];
        sW1d[i].x = pack2(wa, wa);
        sW1d[i].y = pack2(wb, wb);
    }
    for (int i = tid; i < 64; i += THREADS) { float b = b1[i]; sb1d[i] = pack2(b, b); }
    for (int i = tid; i < 64 * 32; i += THREADS) sW2[i] = W2[i];
    for (int i = tid; i < 32; i += THREADS) sb2[i] = b2[i];
    for (int i = tid; i < 32 * 16; i += THREADS) sW3[i] = W3[i];
    for (int i = tid; i < 16; i += THREADS) sb3[i] = b3[i];
    for (int i = tid; i < 16 * 12; i += THREADS) {
        int r = i / 12, c = i % 12;
        sW4[i] = (c < 9) ? W4[r * 9 + c] : 0.0f;
    }
    for (int i = tid; i < 12; i += THREADS) sb4[i] = (i < 9) ? b4[i] : 0.0f;

    // 4 rows per thread: pair AB = (r0, r1), pair CD = (r2, r3)
    int base = blockIdx.x * (4 * THREADS) + tid;
    int r0 = base, r1 = base + THREADS, r2 = base + 2 * THREADS, r3 = base + 3 * THREADS;
    if (r0 >= B) { __syncthreads(); return; }
    if (r1 >= B) r1 = r0;
    if (r2 >= B) r2 = r0;
    if (r3 >= B) r3 = r0;

    // prefetch margins before the barrier to overlap DRAM latency
    const float2* m2 = reinterpret_cast<const float2*>(margins);
    float2 g0 = m2[r0 * 3 + 0], g1 = m2[r0 * 3 + 1], g2 = m2[r0 * 3 + 2];
    float2 h0 = m2[r1 * 3 + 0], h1 = m2[r1 * 3 + 1], h2v = m2[r1 * 3 + 2];
    float2 i0 = m2[r2 * 3 + 0], i1 = m2[r2 * 3 + 1], i2 = m2[r2 * 3 + 2];
    float2 j0 = m2[r3 * 3 + 0], j1 = m2[r3 * 3 + 1], j2 = m2[r3 * 3 + 2];
    float xA[6] = { g0.x, g0.y, g1.x, g1.y, g2.x, g2.y };
    float xB[6] = { h0.x, h0.y, h1.x, h1.y, h2v.x, h2v.y };
    float xC[6] = { i0.x, i0.y, i1.x, i1.y, i2.x, i2.y };
    float xD[6] = { j0.x, j0.y, j1.x, j1.y, j2.x, j2.y };

    __syncthreads();

    ull pxAB[6], pxCD[6];
    #pragma unroll
    for (int i = 0; i < 6; i++) { pxAB[i] = pack2(xA[i], xB[i]); pxCD[i] = pack2(xC[i], xD[i]); }

    // ---- fused L1 (6->64) + L2 (64->32), output-packed accumulators ----
    ull accA[16], accB[16], accC[16], accD[16];
    {
        const ulonglong2* bias = reinterpret_cast<const ulonglong2*>(sb2);
        #pragma unroll
        for (int q = 0; q < 8; q++) {
            ulonglong2 t = bias[q];
            accA[2*q] = t.x; accA[2*q+1] = t.y;
            accB[2*q] = t.x; accB[2*q+1] = t.y;
            accC[2*q] = t.x; accC[2*q+1] = t.y;
            accD[2*q] = t.x; accD[2*q+1] = t.y;
        }
    }
    #pragma unroll 4
    for (int j = 0; j < 64; j++) {
        ulonglong2 w10 = sW1d[j*3+0], w11 = sW1d[j*3+1], w12 = sW1d[j*3+2];
        ull bj = sb1d[j];
        ull hAB = bj, hCD = bj;
        hAB = fma2(pxAB[0], w10.x, hAB);  hCD = fma2(pxCD[0], w10.x, hCD);
        hAB = fma2(pxAB[1], w10.y, hAB);  hCD = fma2(pxCD[1], w10.y, hCD);
        hAB = fma2(pxAB[2], w11.x, hAB);  hCD = fma2(pxCD[2], w11.x, hCD);
        hAB = fma2(pxAB[3], w11.y, hAB);  hCD = fma2(pxCD[3], w11.y, hCD);
        hAB = fma2(pxAB[4], w12.x, hAB);  hCD = fma2(pxCD[4], w12.x, hCD);
        hAB = fma2(pxAB[5], w12.y, hAB);  hCD = fma2(pxCD[5], w12.y, hCD);
        float ha, hb, hc, hd;
        unpack2(hAB, ha, hb); unpack2(hCD, hc, hd);
        ha = fmaxf(ha, 0.0f); hb = fmaxf(hb, 0.0f);
        hc = fmaxf(hc, 0.0f); hd = fmaxf(hd, 0.0f);
        ull pa = pack2(ha, ha), pb = pack2(hb, hb);
        ull pc = pack2(hc, hc), pd = pack2(hd, hd);
        const ulonglong2* w2 = reinterpret_cast<const ulonglong2*>(sW2 + j * 32);
        #pragma unroll
        for (int q = 0; q < 8; q++) {
            ulonglong2 w = w2[q];
            accA[2*q]   = fma2(pa, w.x, accA[2*q]);
            accA[2*q+1] = fma2(pa, w.y, accA[2*q+1]);
            accB[2*q]   = fma2(pb, w.x, accB[2*q]);
            accB[2*q+1] = fma2(pb, w.y, accB[2*q+1]);
            accC[2*q]   = fma2(pc, w.x, accC[2*q]);
            accC[2*q+1] = fma2(pc, w.y, accC[2*q+1]);
            accD[2*q]   = fma2(pd, w.x, accD[2*q]);
            accD[2*q+1] = fma2(pd, w.y, accD[2*q+1]);
        }
    }

    // ---- L3 (32->16) ----
    ull h3A[8], h3B[8], h3C[8], h3D[8];
    {
        const ulonglong2* bias = reinterpret_cast<const ulonglong2*>(sb3);
        #pragma unroll
        for (int q = 0; q < 4; q++) {
            ulonglong2 t = bias[q];
            h3A[2*q] = t.x; h3A[2*q+1] = t.y;
            h3B[2*q] = t.x; h3B[2*q+1] = t.y;
            h3C[2*q] = t.x; h3C[2*q+1] = t.y;
            h3D[2*q] = t.x; h3D[2*q+1] = t.y;
        }
    }
    #pragma unroll 2
    for (int jp = 0; jp < 16; jp++) {
        float a0f, a1f, b0f, b1f, c0f, c1f, d0f, d1f;
        unpack2(accA[jp], a0f, a1f); unpack2(accB[jp], b0f, b1f);
        unpack2(accC[jp], c0f, c1f); unpack2(accD[jp], d0f, d1f);
        a0f = fmaxf(a0f, 0.0f); a1f = fmaxf(a1f, 0.0f);
        b0f = fmaxf(b0f, 0.0f); b1f = fmaxf(b1f, 0.0f);
        c0f = fmaxf(c0f, 0.0f); c1f = fmaxf(c1f, 0.0f);
        d0f = fmaxf(d0f, 0.0f); d1f = fmaxf(d1f, 0.0f);
        #pragma unroll
        for (int s = 0; s < 2; s++) {
            int j = 2 * jp + s;
            ull pa = pack2(s ? a1f : a0f, s ? a1f : a0f);
            ull pb = pack2(s ? b1f : b0f, s ? b1f : b0f);
            ull pc = pack2(s ? c1f : c0f, s ? c1f : c0f);
            ull pd = pack2(s ? d1f : d0f, s ? d1f : d0f);
            const ulonglong2* w3 = reinterpret_cast<const ulonglong2*>(sW3 + j * 16);
            #pragma unroll
            for (int q = 0; q < 4; q++) {
                ulonglong2 w = w3[q];
                h3A[2*q]   = fma2(pa, w.x, h3A[2*q]);
                h3A[2*q+1] = fma2(pa, w.y, h3A[2*q+1]);
                h3B[2*q]   = fma2(pb, w.x, h3B[2*q]);
                h3B[2*q+1] = fma2(pb, w.y, h3B[2*q+1]);
                h3C[2*q]   = fma2(pc, w.x, h3C[2*q]);
                h3C[2*q+1] = fma2(pc, w.y, h3C[2*q+1]);
                h3D[2*q]   = fma2(pd, w.x, h3D[2*q]);
                h3D[2*q+1] = fma2(pd, w.y, h3D[2*q+1]);
            }
        }
    }

    // ---- L4 (16->9, padded 12) ----
    ull p4A[6], p4B[6], p4C[6], p4D[6];
    {
        const ulonglong2* bias = reinterpret_cast<const ulonglong2*>(sb4);
        #pragma unroll
        for (int q = 0; q < 3; q++) {
            ulonglong2 t = bias[q];
            p4A[2*q] = t.x; p4A[2*q+1] = t.y;
            p4B[2*q] = t.x; p4B[2*q+1] = t.y;
            p4C[2*q] = t.x; p4C[2*q+1] = t.y;
            p4D[2*q] = t.x; p4D[2*q+1] = t.y;
        }
    }
    #pragma unroll 2
    for (int jp = 0; jp < 8; jp++) {
        float a0f, a1f, b0f, b1f, c0f, c1f, d0f, d1f;
        unpack2(h3A[jp], a0f, a1f); unpack2(h3B[jp], b0f, b1f);
        unpack2(h3C[jp], c0f, c1f); unpack2(h3D[jp], d0f, d1f);
        a0f = fmaxf(a0f, 0.0f); a1f = fmaxf(a1f, 0.0f);
        b0f = fmaxf(b0f, 0.0f); b1f = fmaxf(b1f, 0.0f);
        c0f = fmaxf(c0f, 0.0f); c1f = fmaxf(c1f, 0.0f);
        d0f = fmaxf(d0f, 0.0f); d1f = fmaxf(d1f, 0.0f);
        #pragma unroll
        for (int s = 0; s < 2; s++) {
            int j = 2 * jp + s;
            ull pa = pack2(s ? a1f : a0f, s ? a1f : a0f);
            ull pb = pack2(s ? b1f : b0f, s ? b1f : b0f);
            ull pc = pack2(s ? c1f : c0f, s ? c1f : c0f);
            ull pd = pack2(s ? d1f : d0f, s ? d1f : d0f);
            const ulonglong2* w4 = reinterpret_cast<const ulonglong2*>(sW4 + j * 12);
            #pragma unroll
            for (int q = 0; q < 3; q++) {
                ulonglong2 w = w4[q];
                p4A[2*q]   = fma2(pa, w.x, p4A[2*q]);
                p4A[2*q+1] = fma2(pa, w.y, p4A[2*q+1]);
                p4B[2*q]   = fma2(pb, w.x, p4B[2*q]);
                p4B[2*q+1] = fma2(pb, w.y, p4B[2*q+1]);
                p4C[2*q]   = fma2(pc, w.x, p4C[2*q]);
                p4C[2*q+1] = fma2(pc, w.y, p4C[2*q+1]);
                p4D[2*q]   = fma2(pd, w.x, p4D[2*q]);
                p4D[2*q+1] = fma2(pd, w.y, p4D[2*q+1]);
            }
        }
    }

    float parsA[12], parsB[12], parsC[12], parsD[12];
    #pragma unroll
    for (int q = 0; q < 6; q++) {
        unpack2(p4A[q], parsA[2*q], parsA[2*q+1]);
        unpack2(p4B[q], parsB[2*q], parsB[2*q+1]);
        unpack2(p4C[q], parsC[2*q], parsC[2*q+1]);
        unpack2(p4D[q], parsD[2*q], parsD[2*q+1]);
    }

    head2(xA, xB, parsA, parsB, out_mus, out_V, r0, r1);
    head2(xC, xD, parsC, parsD, out_mus, out_V, r2, r3);
}

extern "C" void kernel_launch(void* const* d_in, const int* in_sizes, int n_in,
                              void* d_out, int out_size)
{
    const float* margins = (const float*)d_in[0];
    const float* W1 = (const float*)d_in[1];
    const float* b1 = (const float*)d_in[2];
    const float* W2 = (const float*)d_in[3];
    const float* b2 = (const float*)d_in[4];
    const float* W3 = (const float*)d_in[5];
    const float* b3 = (const float*)d_in[6];
    const float* W4 = (const float*)d_in[7];
    const float* b4 = (const float*)d_in[8];

    int B = in_sizes[0] / 6;
    float* out_mus = (float*)d_out;
    float* out_V = (float*)d_out + (size_t)B * 16;

    int rows_per_block = 4 * THREADS;
    int blocks = (B + rows_per_block - 1) / rows_per_block;
    sinkhorn_unmatched_kernel<<<blocks, THREADS>>>(
        margins, W1, b1, W2, b2, W3, b3, W4, b4, out_mus, out_V, B);
}

// round 6
// speedup vs baseline: 1.3841x; 1.3841x over previous
#include <cuda_runtime.h>

#define THREADS 128
#define EPSF 1e-12f

typedef unsigned long long ull;

// ---- f32x2 packed helpers (sm_103a) ----
__device__ __forceinline__ ull pack2(float lo, float hi) {
    ull r; asm("mov.b64 %0, {%1, %2};" : "=l"(r) : "f"(lo), "f"(hi)); return r;
}
__device__ __forceinline__ void unpack2(ull p, float& lo, float& hi) {
    asm("mov.b64 {%0, %1}, %2;" : "=f"(lo), "=f"(hi) : "l"(p));
}
__device__ __forceinline__ ull fma2(ull a, ull b, ull c) {
    ull d; asm("fma.rn.f32x2 %0, %1, %2, %3;" : "=l"(d) : "l"(a), "l"(b), "l"(c)); return d;
}
__device__ __forceinline__ ull add2(ull a, ull b) {
    ull d; asm("add.rn.f32x2 %0, %1, %2;" : "=l"(d) : "l"(a), "l"(b)); return d;
}
__device__ __forceinline__ ull mul2(ull a, ull b) {
    ull d; asm("mul.rn.f32x2 %0, %1, %2;" : "=l"(d) : "l"(a), "l"(b)); return d;
}
__device__ __forceinline__ float frcp(float x) {
    float y; asm("rcp.approx.f32 %0, %1;" : "=f"(y) : "f"(x)); return y;
}

__global__ __launch_bounds__(THREADS, 5)
void sinkhorn_unmatched_kernel(
    const float* __restrict__ margins,
    const float* __restrict__ W1, const float* __restrict__ b1,
    const float* __restrict__ W2, const float* __restrict__ b2,
    const float* __restrict__ W3, const float* __restrict__ b3,
    const float* __restrict__ W4, const float* __restrict__ b4,
    float* __restrict__ out_mus, float* __restrict__ out_V, int B)
{
    // W1 transposed into output-pair rows: sW1t[j][2*i+s] = W1[i][2j+s]
    // (12 floats per pair j, 48B stride keeps 16B alignment for LDS.128)
    __shared__ float sW1t[32 * 12];
    __shared__ ull   sb1p[32];        // (b1[2j], b1[2j+1])
    __shared__ float sW2[64 * 32];    // raw rows
    __shared__ float sb2[32];
    __shared__ float sW3[32 * 16];    // raw rows
    __shared__ float sb3[16];
    __shared__ float sW4[16 * 12];    // rows padded 9 -> 12
    __shared__ float sb4[12];

    const int tid = threadIdx.x;
    for (int i = tid; i < 32 * 12; i += THREADS) {
        int j = i / 12, t = i % 12;
        int in = t >> 1, s = t & 1;
        sW1t[i] = W1[in * 64 + 2 * j + s];
    }
    for (int i = tid; i < 32; i += THREADS) sb1p[i] = pack2(b1[2 * i], b1[2 * i + 1]);
    for (int i = tid; i < 64 * 32; i += THREADS) sW2[i] = W2[i];
    for (int i = tid; i < 32; i += THREADS) sb2[i] = b2[i];
    for (int i = tid; i < 32 * 16; i += THREADS) sW3[i] = W3[i];
    for (int i = tid; i < 16; i += THREADS) sb3[i] = b3[i];
    for (int i = tid; i < 16 * 12; i += THREADS) {
        int r = i / 12, c = i % 12;
        sW4[i] = (c < 9) ? W4[r * 9 + c] : 0.0f;
    }
    for (int i = tid; i < 12; i += THREADS) sb4[i] = (i < 9) ? b4[i] : 0.0f;

    int row = blockIdx.x * THREADS + tid;
    if (row >= B) { __syncthreads(); return; }

    // prefetch margins before barrier
    const float2* m2 = reinterpret_cast<const float2*>(margins);
    float2 ma = m2[row * 3 + 0];
    float2 mb = m2[row * 3 + 1];
    float2 mc = m2[row * 3 + 2];
    float x[6] = { ma.x, ma.y, mb.x, mb.y, mc.x, mc.y };

    __syncthreads();

    // broadcast-packed inputs (x_i, x_i)
    ull px[6];
    #pragma unroll
    for (int i = 0; i < 6; i++) px[i] = pack2(x[i], x[i]);

    // ---- fused L1 (6->64) + L2 (64->32); acc = 16 output-pairs of layer 2 ----
    ull acc[16];
    {
        const ulonglong2* bias = reinterpret_cast<const ulonglong2*>(sb2);
        #pragma unroll
        for (int q = 0; q < 8; q++) {
            ulonglong2 t = bias[q];
            acc[2 * q] = t.x; acc[2 * q + 1] = t.y;
        }
    }
    #pragma unroll 8
    for (int jp = 0; jp < 32; jp++) {
        const ulonglong2* w1 = reinterpret_cast<const ulonglong2*>(sW1t + jp * 12);
        ulonglong2 wa = w1[0], wb = w1[1], wc = w1[2];
        ull h = sb1p[jp];
        h = fma2(px[0], wa.x, h);
        h = fma2(px[1], wa.y, h);
        h = fma2(px[2], wb.x, h);
        h = fma2(px[3], wb.y, h);
        h = fma2(px[4], wc.x, h);
        h = fma2(px[5], wc.y, h);
        float h0, h1; unpack2(h, h0, h1);
        h0 = fmaxf(h0, 0.0f); h1 = fmaxf(h1, 0.0f);
        ull p0 = pack2(h0, h0), p1 = pack2(h1, h1);
        const ulonglong2* w2a = reinterpret_cast<const ulonglong2*>(sW2 + (2 * jp) * 32);
        const ulonglong2* w2b = reinterpret_cast<const ulonglong2*>(sW2 + (2 * jp + 1) * 32);
        #pragma unroll
        for (int q = 0; q < 8; q++) {
            ulonglong2 u = w2a[q];
            acc[2 * q]     = fma2(p0, u.x, acc[2 * q]);
            acc[2 * q + 1] = fma2(p0, u.y, acc[2 * q + 1]);
        }
        #pragma unroll
        for (int q = 0; q < 8; q++) {
            ulonglong2 u = w2b[q];
            acc[2 * q]     = fma2(p1, u.x, acc[2 * q]);
            acc[2 * q + 1] = fma2(p1, u.y, acc[2 * q + 1]);
        }
    }

    // ---- L3 (32->16): 8 output-pairs ----
    ull h3[8];
    {
        const ulonglong2* bias = reinterpret_cast<const ulonglong2*>(sb3);
        #pragma unroll
        for (int q = 0; q < 4; q++) {
            ulonglong2 t = bias[q];
            h3[2 * q] = t.x; h3[2 * q + 1] = t.y;
        }
    }
    #pragma unroll 4
    for (int p = 0; p < 16; p++) {
        float h0, h1; unpack2(acc[p], h0, h1);
        h0 = fmaxf(h0, 0.0f); h1 = fmaxf(h1, 0.0f);
        ull p0 = pack2(h0, h0), p1 = pack2(h1, h1);
        const ulonglong2* wa = reinterpret_cast<const ulonglong2*>(sW3 + (2 * p) * 16);
        const ulonglong2* wb = reinterpret_cast<const ulonglong2*>(sW3 + (2 * p + 1) * 16);
        #pragma unroll
        for (int q = 0; q < 4; q++) {
            ulonglong2 u = wa[q];
            h3[2 * q]     = fma2(p0, u.x, h3[2 * q]);
            h3[2 * q + 1] = fma2(p0, u.y, h3[2 * q + 1]);
        }
        #pragma unroll
        for (int q = 0; q < 4; q++) {
            ulonglong2 u = wb[q];
            h3[2 * q]     = fma2(p1, u.x, h3[2 * q]);
            h3[2 * q + 1] = fma2(p1, u.y, h3[2 * q + 1]);
        }
    }

    // ---- L4 (16->9 padded 12): 6 output-pairs ----
    ull p4[6];
    {
        const ulonglong2* bias = reinterpret_cast<const ulonglong2*>(sb4);
        #pragma unroll
        for (int q = 0; q < 3; q++) {
            ulonglong2 t = bias[q];
            p4[2 * q] = t.x; p4[2 * q + 1] = t.y;
        }
    }
    #pragma unroll 4
    for (int p = 0; p < 8; p++) {
        float h0, h1; unpack2(h3[p], h0, h1);
        h0 = fmaxf(h0, 0.0f); h1 = fmaxf(h1, 0.0f);
        ull p0 = pack2(h0, h0), p1 = pack2(h1, h1);
        const ulonglong2* wa = reinterpret_cast<const ulonglong2*>(sW4 + (2 * p) * 12);
        const ulonglong2* wb = reinterpret_cast<const ulonglong2*>(sW4 + (2 * p + 1) * 12);
        #pragma unroll
        for (int q = 0; q < 3; q++) {
            ulonglong2 u = wa[q];
            p4[2 * q]     = fma2(p0, u.x, p4[2 * q]);
            p4[2 * q + 1] = fma2(p0, u.y, p4[2 * q + 1]);
        }
        #pragma unroll
        for (int q = 0; q < 3; q++) {
            ulonglong2 u = wb[q];
            p4[2 * q]     = fma2(p1, u.x, p4[2 * q]);
            p4[2 * q + 1] = fma2(p1, u.y, p4[2 * q + 1]);
        }
    }

    float pars[12];
    #pragma unroll
    for (int q = 0; q < 6; q++) unpack2(p4[q], pars[2 * q], pars[2 * q + 1]);

    // ---- head math; Sinkhorn packed over column pairs (col0,col1) + scalar col2 ----
    float M0 = x[0], M1 = x[1], M2 = x[2];
    float F0 = x[3], F1 = x[4], F2 = x[5];

    ull R0 = pack2(__expf(pars[0]), __expf(pars[1]));
    ull R1 = pack2(__expf(pars[2]), __expf(pars[3]));
    ull R2 = pack2(1.0f, 1.0f);
    float a02 = 1.0f, a12 = 1.0f, a22 = 1.0f;

    float shm0 = 0.02f + 0.96f * frcp(1.0f + __expf(-pars[4]));
    float shm1 = 0.02f + 0.96f * frcp(1.0f + __expf(-pars[5]));
    float shf0 = 0.02f + 0.96f * frcp(1.0f + __expf(-pars[6]));
    float shf1 = 0.02f + 0.96f * frcp(1.0f + __expf(-pars[7]));
    float V = __expf(pars[8]);

    float r0 = M0 * shm0, r1 = M1 * shm1, r2 = M2;
    ull  cp = pack2(F0 * shf0, F1 * shf1);
    float c2 = F2;
    float um0 = M0 * (1.0f - shm0), um1 = M1 * (1.0f - shm1);
    float uf0 = F0 * (1.0f - shf0), uf1 = F1 * (1.0f - shf1);

    const ull EPS2 = pack2(EPSF, EPSF);

    #pragma unroll
    for (int it = 0; it < 10; it++) {
        // row normalize
        float u, v;
        unpack2(R0, u, v); float f0 = r0 * frcp(u + v + a02 + EPSF);
        unpack2(R1, u, v); float f1 = r1 * frcp(u + v + a12 + EPSF);
        unpack2(R2, u, v); float f2 = r2 * frcp(u + v + a22 + EPSF);
        R0 = mul2(R0, pack2(f0, f0)); a02 *= f0;
        R1 = mul2(R1, pack2(f1, f1)); a12 *= f1;
        R2 = mul2(R2, pack2(f2, f2)); a22 *= f2;
        // column normalize (cols 0,1 packed; col 2 scalar)
        ull s01 = add2(add2(R0, R1), add2(R2, EPS2));
        float s2 = a02 + a12 + a22 + EPSF;
        unpack2(s01, u, v);
        ull g01 = mul2(cp, pack2(frcp(u), frcp(v)));
        float g2 = c2 * frcp(s2);
        R0 = mul2(R0, g01); R1 = mul2(R1, g01); R2 = mul2(R2, g01);
        a02 *= g2; a12 *= g2; a22 *= g2;
    }

    float a00, a01, a10, a11, a20, a21;
    unpack2(R0, a00, a01);
    unpack2(R1, a10, a11);
    unpack2(R2, a20, a21);

    float4* o = reinterpret_cast<float4*>(out_mus + (size_t)row * 16);
    o[0] = make_float4(a00, a01, a02, um0);
    o[1] = make_float4(a10, a11, a12, um1);
    o[2] = make_float4(a20, a21, a22, 0.0f);
    o[3] = make_float4(uf0, uf1, 0.0f, 0.0f);
    out_V[row] = V;
}

extern "C" void kernel_launch(void* const* d_in, const int* in_sizes, int n_in,
                              void* d_out, int out_size)
{
    const float* margins = (const float*)d_in[0];
    const float* W1 = (const float*)d_in[1];
    const float* b1 = (const float*)d_in[2];
    const float* W2 = (const float*)d_in[3];
    const float* b2 = (const float*)d_in[4];
    const float* W3 = (const float*)d_in[5];
    const float* b3 = (const float*)d_in[6];
    const float* W4 = (const float*)d_in[7];
    const float* b4 = (const float*)d_in[8];

    int B = in_sizes[0] / 6;
    float* out_mus = (float*)d_out;
    float* out_V = (float*)d_out + (size_t)B * 16;

    int blocks = (B + THREADS - 1) / THREADS;
    sinkhorn_unmatched_kernel<<<blocks, THREADS>>>(
        margins, W1, b1, W2, b2, W3, b3, W4, b4, out_mus, out_V, B);
}